// round 1
// baseline (speedup 1.0000x reference)
#include <cuda_runtime.h>

#define BB   16
#define CIN  32
#define COUT 32
#define HH   256
#define WW   256
// rows for the two big GEMMs
#define RFW (BB*CIN*HH)    // 131072
#define RIV (BB*COUT*HH)   // 131072

// ---------------- scratch (device globals; no cudaMalloc) ----------------
__device__ float  g_T[256*32];                       // fwd w-DFT table [w][2ky|2ky+1]
__device__ float  g_U[32*256];                       // inv w-DFT table [n][w]
__device__ float2 g_wpack[512*32*32];                // [mode][i][o]
__device__ float2 g_G[(size_t)BB*CIN*HH*16];         // [b,i,h][ky]      16 MB
__device__ float2 g_Xft[BB*CIN*32*16];               // [b,i][kxidx][ky]
__device__ float2 g_Yft[BB*COUT*32*16];              // [b,o][kxidx][ky]
__device__ float  g_Zp[(size_t)BB*COUT*HH*32];       // [b,o,h][2ky|2ky+1] 16 MB

__device__ __forceinline__ float2 cmul(float2 a, float2 b) {
    return make_float2(a.x*b.x - a.y*b.y, a.x*b.y + a.y*b.x);
}

// ---------------- twiddle tables ----------------
__global__ void init_tables() {
    int idx = blockIdx.x * blockDim.x + threadIdx.x;
    if (idx < 256*32) {                 // T[w][n]: n=2ky -> cos, n=2ky+1 -> -sin  (angle 2*pi*ky*w/256)
        int w = idx >> 5, n = idx & 31, ky = n >> 1;
        int t = (ky * w) & 255;
        float s, c;
        sincospif(t * (1.0f/128.0f), &s, &c);
        g_T[idx] = (n & 1) ? -s : c;
    } else if (idx < 2*256*32) {        // U[n][w]: irfft coeffs, scaled by 1/(H*W)
        int j = idx - 256*32;
        int n = j >> 8, w = j & 255, ky = n >> 1;
        int t = (ky * w) & 255;
        float s, c;
        sincospif(t * (1.0f/128.0f), &s, &c);
        float coef = ((ky == 0) ? 1.0f : 2.0f) * (1.0f/65536.0f);
        g_U[j] = (n & 1) ? -coef * s : coef * c;
    }
}

// ---------------- weight repack: [Cin][Cout][m1][m2] -> [mode][i][o] ----------------
__global__ void repack_w(const float* __restrict__ w1r, const float* __restrict__ w1i,
                         const float* __restrict__ w2r, const float* __restrict__ w2i) {
    int idx = blockIdx.x * blockDim.x + threadIdx.x;   // 512*1024
    if (idx >= 512*1024) return;
    int o = idx & 31, i = (idx >> 5) & 31, mode = idx >> 10;
    int ky = mode & 15, kxidx = mode >> 4;
    int x = kxidx & 15;
    int src = ((i*32 + o)*16 + x)*16 + ky;
    float re = (kxidx < 16) ? w1r[src] : w2r[src];
    float im = (kxidx < 16) ? w1i[src] : w2i[src];
    g_wpack[idx] = make_float2(re, im);
}

// ---------------- stage 1: forward w-DFT  G = X * T  (M=131072, K=256, N=32) ----------------
__global__ __launch_bounds__(128) void fwd_wdft(const float* __restrict__ x) {
    __shared__ float As[64][33];
    __shared__ float Ts[32][32];
    int r0  = blockIdx.x * 64;
    int tid = threadIdx.x;
    int tm  = tid >> 3;   // 0..15 -> rows tm*4..tm*4+3
    int tn  = tid & 7;    // 0..7  -> cols tn*4..tn*4+3
    float acc[4][4] = {};

    for (int kt = 0; kt < 8; kt++) {
        #pragma unroll
        for (int p = 0; p < 4; p++) {
            int idx = tid + p*128;
            int lr = idx >> 3, c4 = idx & 7;
            float4 v = *(const float4*)&x[(size_t)(r0 + lr)*256 + kt*32 + c4*4];
            As[lr][c4*4+0] = v.x; As[lr][c4*4+1] = v.y;
            As[lr][c4*4+2] = v.z; As[lr][c4*4+3] = v.w;
        }
        #pragma unroll
        for (int p = 0; p < 2; p++) {
            int idx = tid + p*128;
            int kk = idx >> 3, n4 = idx & 7;
            *(float4*)&Ts[kk][n4*4] = *(const float4*)&g_T[(kt*32 + kk)*32 + n4*4];
        }
        __syncthreads();
        #pragma unroll
        for (int kk = 0; kk < 32; kk++) {
            float a0 = As[tm*4+0][kk], a1 = As[tm*4+1][kk];
            float a2 = As[tm*4+2][kk], a3 = As[tm*4+3][kk];
            float4 b = *(float4*)&Ts[kk][tn*4];
            acc[0][0] += a0*b.x; acc[0][1] += a0*b.y; acc[0][2] += a0*b.z; acc[0][3] += a0*b.w;
            acc[1][0] += a1*b.x; acc[1][1] += a1*b.y; acc[1][2] += a1*b.z; acc[1][3] += a1*b.w;
            acc[2][0] += a2*b.x; acc[2][1] += a2*b.y; acc[2][2] += a2*b.z; acc[2][3] += a2*b.w;
            acc[3][0] += a3*b.x; acc[3][1] += a3*b.y; acc[3][2] += a3*b.z; acc[3][3] += a3*b.w;
        }
        __syncthreads();
    }
    float* Gf = (float*)g_G;
    #pragma unroll
    for (int j = 0; j < 4; j++) {
        float4 v = make_float4(acc[j][0], acc[j][1], acc[j][2], acc[j][3]);
        *(float4*)&Gf[(size_t)(r0 + tm*4 + j)*32 + tn*4] = v;
    }
}

// ---------------- stage 2: forward h-DFT (32 kx bins) ----------------
__global__ __launch_bounds__(256) void fwd_hdft() {
    __shared__ float2 sG[256*16];   // 32 KB
    int bi  = blockIdx.x;           // b*32+i
    int tid = threadIdx.x;
    const float2* Gsrc = &g_G[(size_t)bi * 256 * 16];
    #pragma unroll
    for (int p = 0; p < 16; p++) sG[tid + p*256] = Gsrc[tid + p*256];
    __syncthreads();

    int ky  = tid & 15;
    int kxa = tid >> 4;        // 0..15
    int kxb = 240 + kxa;       // 240..255
    float sa, ca, sb, cb;
    sincospif(kxa * (1.0f/128.0f), &sa, &ca);
    sincospif(kxb * (1.0f/128.0f), &sb, &cb);
    float2 stepa = make_float2(ca, -sa);   // e^{-2*pi*i*kx/256}
    float2 stepb = make_float2(cb, -sb);
    float2 twa = make_float2(1.f, 0.f), twb = make_float2(1.f, 0.f);
    float2 acca = make_float2(0.f, 0.f), accb = make_float2(0.f, 0.f);

    #pragma unroll 4
    for (int h = 0; h < 256; h++) {
        float2 g = sG[h*16 + ky];
        acca.x += g.x*twa.x - g.y*twa.y;
        acca.y += g.x*twa.y + g.y*twa.x;
        accb.x += g.x*twb.x - g.y*twb.y;
        accb.y += g.x*twb.y + g.y*twb.x;
        twa = cmul(twa, stepa);
        twb = cmul(twb, stepb);
    }
    g_Xft[(bi*32 + kxa)*16 + ky]      = acca;
    g_Xft[(bi*32 + 16 + kxa)*16 + ky] = accb;
}

// ---------------- stage 3: channel mix (complex 32x32 per mode) ----------------
__global__ __launch_bounds__(256) void chan_mix() {
    __shared__ float2 sW[32*32];   // [i][o]
    __shared__ float2 sX[16*32];   // [b][i]
    int mode  = blockIdx.x;        // kxidx*16+ky
    int kxidx = mode >> 4, ky = mode & 15;
    int tid   = threadIdx.x;

    #pragma unroll
    for (int p = 0; p < 4; p++) sW[tid + p*256] = g_wpack[mode*1024 + tid + p*256];
    sX[tid % 512]           = g_Xft[(tid*32 + kxidx)*16 + ky];            // tid 0..255 -> entries 0..255
    sX[(tid + 256) % 512]   = g_Xft[((tid + 256)*32 + kxidx)*16 + ky];    // entries 256..511
    __syncthreads();

    int o = tid & 31, b0 = tid >> 5;   // b0 0..7
    float2 acc0 = make_float2(0.f, 0.f), acc1 = make_float2(0.f, 0.f);
    #pragma unroll
    for (int i = 0; i < 32; i++) {
        float2 wv = sW[i*32 + o];
        float2 x0 = sX[b0*32 + i];
        float2 x1 = sX[(b0 + 8)*32 + i];
        acc0.x += x0.x*wv.x - x0.y*wv.y; acc0.y += x0.x*wv.y + x0.y*wv.x;
        acc1.x += x1.x*wv.x - x1.y*wv.y; acc1.y += x1.x*wv.y + x1.y*wv.x;
    }
    g_Yft[((b0*32 + o)*32 + kxidx)*16 + ky]       = acc0;
    g_Yft[(((b0 + 8)*32 + o)*32 + kxidx)*16 + ky] = acc1;
}

// ---------------- stage 4: inverse h-DFT -> Zp ----------------
__global__ __launch_bounds__(256) void inv_hdft() {
    __shared__ float2 sY[512];     // [kxidx][ky]
    int bo  = blockIdx.x;
    int tid = threadIdx.x;         // = h
    sY[tid]       = g_Yft[bo*512 + tid];
    sY[tid + 256] = g_Yft[bo*512 + tid + 256];
    __syncthreads();

    float s, c;
    sincospif(tid * (1.0f/128.0f), &s, &c);
    float2 step = make_float2(c, s);       // e^{+2*pi*i*h/256}
    float accr[16] = {}, acci[16] = {};
    float2 cur = make_float2(1.f, 0.f);

    #pragma unroll 4
    for (int j = 0; j < 16; j++) {         // kx = 0..15
        #pragma unroll
        for (int ky = 0; ky < 16; ky++) {
            float2 y = sY[j*16 + ky];
            accr[ky] += y.x*cur.x - y.y*cur.y;
            acci[ky] += y.x*cur.y + y.y*cur.x;
        }
        cur = cmul(cur, step);
    }
    float2 cur2 = make_float2(cur.x, -cur.y);   // step^{-16} == e^{2*pi*i*240*h/256}
    #pragma unroll 4
    for (int j = 0; j < 16; j++) {         // kx = 240..255
        #pragma unroll
        for (int ky = 0; ky < 16; ky++) {
            float2 y = sY[(16 + j)*16 + ky];
            accr[ky] += y.x*cur2.x - y.y*cur2.y;
            acci[ky] += y.x*cur2.y + y.y*cur2.x;
        }
        cur2 = cmul(cur2, step);
    }
    float* Z = &g_Zp[((size_t)bo*256 + tid)*32];
    #pragma unroll
    for (int ky = 0; ky < 8; ky++) {
        float4 v0 = make_float4(accr[2*ky], acci[2*ky], accr[2*ky+1], acci[2*ky+1]);
        *(float4*)&Z[4*ky] = v0;
    }
}

// ---------------- stage 5: inverse w-DFT  out = Zp * U  (M=131072, K=32, N=256) ----------------
__global__ __launch_bounds__(256) void inv_wdft(float* __restrict__ out) {
    __shared__ float As[64][33];
    __shared__ float Bs[32][64];
    int r0  = blockIdx.x * 64;
    int w0  = blockIdx.y * 64;
    int tid = threadIdx.x;

    #pragma unroll
    for (int p = 0; p < 2; p++) {
        int idx = tid + p*256;
        int lr = idx >> 3, c4 = idx & 7;
        float4 v = *(const float4*)&g_Zp[(size_t)(r0 + lr)*32 + c4*4];
        As[lr][c4*4+0] = v.x; As[lr][c4*4+1] = v.y;
        As[lr][c4*4+2] = v.z; As[lr][c4*4+3] = v.w;
    }
    #pragma unroll
    for (int p = 0; p < 2; p++) {
        int idx = tid + p*256;
        int kk = idx >> 4, c4 = idx & 15;
        *(float4*)&Bs[kk][c4*4] = *(const float4*)&g_U[kk*256 + w0 + c4*4];
    }
    __syncthreads();

    int tm = tid >> 4;   // 0..15
    int tn = tid & 15;   // 0..15
    float acc[4][4] = {};
    #pragma unroll
    for (int kk = 0; kk < 32; kk++) {
        float a0 = As[tm*4+0][kk], a1 = As[tm*4+1][kk];
        float a2 = As[tm*4+2][kk], a3 = As[tm*4+3][kk];
        float4 b = *(float4*)&Bs[kk][tn*4];
        acc[0][0] += a0*b.x; acc[0][1] += a0*b.y; acc[0][2] += a0*b.z; acc[0][3] += a0*b.w;
        acc[1][0] += a1*b.x; acc[1][1] += a1*b.y; acc[1][2] += a1*b.z; acc[1][3] += a1*b.w;
        acc[2][0] += a2*b.x; acc[2][1] += a2*b.y; acc[2][2] += a2*b.z; acc[2][3] += a2*b.w;
        acc[3][0] += a3*b.x; acc[3][1] += a3*b.y; acc[3][2] += a3*b.z; acc[3][3] += a3*b.w;
    }
    #pragma unroll
    for (int j = 0; j < 4; j++) {
        float4 v = make_float4(acc[j][0], acc[j][1], acc[j][2], acc[j][3]);
        *(float4*)&out[(size_t)(r0 + tm*4 + j)*256 + w0 + tn*4] = v;
    }
}

// ---------------- launch ----------------
extern "C" void kernel_launch(void* const* d_in, const int* in_sizes, int n_in,
                              void* d_out, int out_size) {
    const float* x   = (const float*)d_in[0];
    const float* w1r = (const float*)d_in[1];
    const float* w1i = (const float*)d_in[2];
    const float* w2r = (const float*)d_in[3];
    const float* w2i = (const float*)d_in[4];
    float* out = (float*)d_out;

    init_tables<<<64, 256>>>();
    repack_w<<<2048, 256>>>(w1r, w1i, w2r, w2i);
    fwd_wdft<<<RFW/64, 128>>>(x);
    fwd_hdft<<<BB*CIN, 256>>>();
    chan_mix<<<512, 256>>>();
    inv_hdft<<<BB*COUT, 256>>>();
    inv_wdft<<<dim3(RIV/64, 4), 256>>>(out);
}